// round 9
// baseline (speedup 1.0000x reference)
#include <cuda_runtime.h>
#include <cuda_fp16.h>
#include <cstdint>

#define H        4096
#define T_TRAIN  2048
#define GRID     148
#define BLOCK    1024         // 28 dot warps + 4 stager warps
#define DOTW     28
#define HMAX     64
#define NCACHE   26           // U-matrix rows cached in SMEM per CTA (big path)
#define ROW_U4   512          // uint4 per weight row (4096 halves = 8 KB)

// ---------------- persistent device state ----------------------------------
__device__ __half   g_wu[(size_t)H * H];   // fp16 weights, PERMUTED layout:
__device__ __half   g_wr[(size_t)H * H];   // chunk j = cols {4j..4j+3, 2048+4j..2048+4j+3}
__device__ __half   g_wc[(size_t)H * H];
__device__ float    g_h[2][H];
__device__ float    g_vhp[HMAX + 1][GRID];
__device__ unsigned g_count;
__device__ unsigned g_phase;

// ---------------- fp32 -> fp16 conversion with column permutation -----------
__global__ void convert_w(const float* __restrict__ u,
                          const float* __restrict__ r,
                          const float* __restrict__ c)
{
    const int total = H * ROW_U4;
    int idx = blockIdx.x * blockDim.x + threadIdx.x;
    if (idx >= total) return;
    const int row = idx >> 9;
    const int j   = idx & 511;
    const int i0  = row * (H / 4) + j;        // float4 index of cols 4j..4j+3
    const int i1  = i0 + 512;                 // float4 index of cols 2048+4j..+3

    #define CVT_ONE(SRC, DST)                                           \
    {                                                                   \
        float4 a = ((const float4*)SRC)[i0];                            \
        float4 b = ((const float4*)SRC)[i1];                            \
        uint4 o;                                                        \
        __half2 t;                                                      \
        t = __floats2half2_rn(a.x, a.y); o.x = *(unsigned*)&t;          \
        t = __floats2half2_rn(a.z, a.w); o.y = *(unsigned*)&t;          \
        t = __floats2half2_rn(b.x, b.y); o.z = *(unsigned*)&t;          \
        t = __floats2half2_rn(b.z, b.w); o.w = *(unsigned*)&t;          \
        ((uint4*)DST)[idx] = o;                                         \
    }
    CVT_ONE(u, g_wu)
    CVT_ONE(r, g_wr)
    CVT_ONE(c, g_wc)
    #undef CVT_ONE
}

// ---------------- grid-wide barrier (single co-resident wave) ---------------
__device__ __forceinline__ void grid_barrier(unsigned &local_phase, int G) {
    __threadfence();
    __syncthreads();
    if (threadIdx.x == 0) {
        unsigned target = local_phase + 1;
        unsigned arrived = atomicAdd(&g_count, 1u) + 1;
        if (arrived == (unsigned)G) {
            atomicExch(&g_count, 0u);
            __threadfence();
            atomicAdd(&g_phase, 1u);
        } else {
            volatile unsigned* ph = &g_phase;
            while (*ph < target) { }
        }
    }
    local_phase++;
    __syncthreads();
    __threadfence();
}

__device__ __forceinline__ float sigmoidf_fast(float z) {
    return 1.0f / (1.0f + __expf(-z));
}

// packed f32x2 fma: acc(lo,hi) += (x0,x1) * (y0,y1); acc carried as u64
__device__ __forceinline__ void ffma2(unsigned long long& acc,
                                      float x0, float x1,
                                      float y0, float y1)
{
    unsigned long long a, b;
    asm("mov.b64 %0, {%1, %2};" : "=l"(a) : "f"(x0), "f"(x1));
    asm("mov.b64 %0, {%1, %2};" : "=l"(b) : "f"(y0), "f"(y1));
    asm("fma.rn.f32x2 %0, %1, %2, %3;" : "=l"(acc) : "l"(a), "l"(b), "l"(acc));
}

__device__ __forceinline__ float hsum2(unsigned long long acc) {
    float lo, hi;
    asm("mov.b64 {%0, %1}, %2;" : "=f"(lo), "=f"(hi) : "l"(acc));
    return lo + hi;
}

// 8 fp16 weights (one uint4, permuted) x matching 8 h values -> packed acc
__device__ __forceinline__ void acc8p(uint4 w, float4 ha, float4 hb,
                                      unsigned long long& acc)
{
    float2 f0 = __half22float2(*(__half2*)&w.x);
    float2 f1 = __half22float2(*(__half2*)&w.y);
    float2 f2 = __half22float2(*(__half2*)&w.z);
    float2 f3 = __half22float2(*(__half2*)&w.w);
    ffma2(acc, f0.x, f0.y, ha.x, ha.y);
    ffma2(acc, f1.x, f1.y, ha.z, ha.w);
    ffma2(acc, f2.x, f2.y, hb.x, hb.y);
    ffma2(acc, f3.x, f3.y, hb.z, hb.w);
}

// spin on 4 per-stager-warp step flags (values are monotone step numbers)
__device__ __forceinline__ void wait_flags(volatile int* f, int t) {
    while (f[0] < t || f[1] < t || f[2] < t || f[3] < t) { }
}

// ---------------- persistent GRU kernel -------------------------------------
__global__ void __launch_bounds__(BLOCK, 1)
gru_persistent(const float* __restrict__ x_seq,
               const float* __restrict__ uwx, const float* __restrict__ ub,
               const float* __restrict__ rwx, const float* __restrict__ rb,
               const float* __restrict__ wx,  const float* __restrict__ bb,
               const float* __restrict__ v,   const float* __restrict__ cc,
               float* __restrict__ out, int horizon, int ncache)
{
    extern __shared__ char smem[];
    float* h_s = (float*)smem;                         // 16 KB
    uint4* ws  = (uint4*)(smem + H * sizeof(float));   // ncache rows of U

    __shared__ float red_s[32];
    __shared__ float x_s;
    __shared__ int   flA[4], flB[4];                   // per-stager-warp flags
    __shared__ int   flX;                              // AR-phase x flag

    const int tid  = threadIdx.x;
    const int b    = blockIdx.x;
    const int G    = gridDim.x;
    const int warp = tid >> 5;
    const int lane = tid & 31;

    const int r0 = (int)(((long long)b       * H) / G);
    const int r1 = (int)(((long long)(b + 1) * H) / G);
    const int nrows = r1 - r0;   // 27 or 28 (<= DOTW)

    if (tid < 4) { flA[tid] = -1; flB[tid] = -1; }
    if (tid == 4) flX = -1;
    if (tid < 32) red_s[tid] = 0.f;

    // prologue: pin first `ncache` U-rows of this CTA into SMEM
    {
        const uint4* src = ((const uint4*)g_wu) + (size_t)r0 * ROW_U4;
        const int n = ncache * ROW_U4;
        for (int i = tid; i < n; i += BLOCK) ws[i] = src[i];
    }

    // matvec row pointers (warp w owns row r0+w for all three matrices)
    const bool mv_active = (warp < nrows);
    const int  myrow = r0 + warp;
    const uint4* pu = nullptr; const uint4* pr = nullptr; const uint4* pc = nullptr;
    if (mv_active) {
        const size_t off = (size_t)myrow * ROW_U4;
        pu = (warp < ncache) ? (ws + (size_t)warp * ROW_U4)
                             : (((const uint4*)g_wu) + off);
        pr = ((const uint4*)g_wr) + off;
        pc = ((const uint4*)g_wc) + off;
    }

    const float c0 = cc[0];
    unsigned phase = 0;
    const int total_steps = T_TRAIN + horizon;
    __syncthreads();   // flags init + ws cache visible to all warps

    for (int t = 0; t < total_steps; ++t) {
        const int par = t & 1;
        const float* hin  = g_h[par];
        float*       hout = g_h[par ^ 1];
        const bool need_y = (t >= T_TRAIN - 1);

        if (warp >= DOTW) {
            // ---- stager warps: copy h in 2 chunks, publish step flags ----
            const int sw  = warp - DOTW;        // 0..3
            const int sid = tid - DOTW * 32;    // 0..127
            const float4* src = (const float4*)hin;
            float4*       dst = (float4*)h_s;
            // chunk A: f4 [0,256) and [512,768)  (dot batches k<8)
            #pragma unroll
            for (int i = sid; i < 256; i += 128) {
                dst[i]       = src[i];
                dst[512 + i] = src[512 + i];
            }
            __syncwarp();
            __threadfence_block();
            if (lane == 0) flA[sw] = t;
            // chunk B: f4 [256,512) and [768,1024)  (dot batches k>=8)
            #pragma unroll
            for (int i = sid; i < 256; i += 128) {
                dst[256 + i] = src[256 + i];
                dst[768 + i] = src[768 + i];
            }
            __syncwarp();
            __threadfence_block();
            if (lane == 0) flB[sw] = t;

            // warp 31: x for AR steps (hidden behind dot latency)
            if (warp == 31 && t >= T_TRAIN) {
                const float* p = g_vhp[t - T_TRAIN];
                float s = 0.f;
                for (int i = lane; i < G; i += 32) s += p[i];
                #pragma unroll
                for (int o = 16; o; o >>= 1)
                    s += __shfl_down_sync(0xffffffffu, s, o);
                if (lane == 0) {
                    x_s = s + c0;
                    __threadfence_block();
                    flX = t;
                }
            }
        } else if (mv_active) {
            // ---- dot warps: fused 3-matrix row-dot, depth-2 weight prefetch,
            //      h gated by chunk flags; weights prefetch across the gate ----
            const float4* h4 = (const float4*)h_s;
            unsigned long long au = 0ull, ar = 0ull, ac = 0ull;

            uint4 wu0 = pu[lane],      wr0 = pr[lane],      wc0 = pc[lane];
            uint4 wu1 = pu[lane + 32], wr1 = pr[lane + 32], wc1 = pc[lane + 32];

            wait_flags(flA, t);
            int j = lane;
            #pragma unroll 4
            for (int k = 0; k < 16; ++k) {
                if (k == 8) wait_flags(flB, t);
                uint4 nu, nr, nc;
                if (k < 14) {
                    const int jp = j + 64;
                    nu = pu[jp]; nr = pr[jp]; nc = pc[jp];
                }
                float4 ha = h4[j];         // stride 16B -> conflict-free
                float4 hb = h4[512 + j];   // stride 16B -> conflict-free
                acc8p(wu0, ha, hb, au);
                acc8p(wr0, ha, hb, ar);
                acc8p(wc0, ha, hb, ac);
                wu0 = wu1; wr0 = wr1; wc0 = wc1;
                wu1 = nu;  wr1 = nr;  wc1 = nc;
                j += 32;
            }

            float su = hsum2(au), sr = hsum2(ar), sc = hsum2(ac);
            #pragma unroll
            for (int o = 16; o; o >>= 1) {
                su += __shfl_down_sync(0xffffffffu, su, o);
                sr += __shfl_down_sync(0xffffffffu, sr, o);
                sc += __shfl_down_sync(0xffffffffu, sc, o);
            }

            // x: direct read during training; flag-gated from warp 31 in AR
            float x;
            if (t < T_TRAIN) {
                x = __ldg(&x_seq[t]);
            } else {
                volatile int* fx = &flX;
                while (*fx < t) { }
                x = x_s;
            }

            // decentralized gate: lane 0 of each dot warp updates its row
            if (lane == 0) {
                const float h_old = h_s[myrow];
                const float u  = sigmoidf_fast(__ldg(&uwx[myrow]) * x + su + __ldg(&ub[myrow]));
                const float r  = sigmoidf_fast(__ldg(&rwx[myrow]) * x + sr + __ldg(&rb[myrow]));
                const float hh = tanhf(__ldg(&wx[myrow]) * x + r * sc + __ldg(&bb[myrow]));
                const float hn = h_old + u * (hh - h_old);
                hout[myrow] = hn;
                if (need_y) red_s[warp] = __ldg(&v[myrow]) * hn;
            }
        }

        // y partial reduction only on the last horizon+1 steps
        if (need_y) {
            __syncthreads();
            if (warp == 0) {
                float yv = (lane < nrows) ? red_s[lane] : 0.f;
                #pragma unroll
                for (int o = 16; o; o >>= 1)
                    yv += __shfl_down_sync(0xffffffffu, yv, o);
                if (lane == 0) g_vhp[t - (T_TRAIN - 1)][b] = yv;
            }
        }

        grid_barrier(phase, G);
    }

    // emit predictions (deterministic final reduction)
    if (b == 0 && tid < horizon) {
        const float* p = g_vhp[tid + 1];
        float s = 0.f;
        for (int i = 0; i < G; ++i) s += p[i];
        out[tid] = s + c0;
    }
}

// ---------------- launch ----------------------------------------------------
extern "C" void kernel_launch(void* const* d_in, const int* in_sizes, int n_in,
                              void* d_out, int out_size)
{
    (void)in_sizes; (void)n_in;
    const float* x_seq = (const float*)d_in[0];
    // d_in[1] is the scalar 'horizon' (int32); we use out_size instead.
    const float* uwx = (const float*)d_in[2];
    const float* uWh = (const float*)d_in[3];
    const float* ub  = (const float*)d_in[4];
    const float* rwx = (const float*)d_in[5];
    const float* rWh = (const float*)d_in[6];
    const float* rb  = (const float*)d_in[7];
    const float* wx  = (const float*)d_in[8];
    const float* Wh  = (const float*)d_in[9];
    const float* bb  = (const float*)d_in[10];
    const float* v   = (const float*)d_in[11];
    const float* cc  = (const float*)d_in[12];

    int horizon = out_size;
    if (horizon > HMAX) horizon = HMAX;

    // reset persistent state (graph-capturable, deterministic per replay)
    void* p;
    cudaGetSymbolAddress(&p, g_h);     cudaMemsetAsync(p, 0, sizeof(float) * 2 * H);
    cudaGetSymbolAddress(&p, g_count); cudaMemsetAsync(p, 0, sizeof(unsigned));
    cudaGetSymbolAddress(&p, g_phase); cudaMemsetAsync(p, 0, sizeof(unsigned));

    // fp32 -> fp16 permuted weight conversion
    {
        const int total = H * ROW_U4;
        convert_w<<<(total + 255) / 256, 256>>>(uWh, rWh, Wh);
    }

    // dyn-smem: try 26-row cache, then 25, then none (same decision every call)
    const int base = H * (int)sizeof(float);
    int ncache = NCACHE;
    int dyn    = base + NCACHE * ROW_U4 * (int)sizeof(uint4);
    cudaError_t e = cudaFuncSetAttribute(gru_persistent,
                                         cudaFuncAttributeMaxDynamicSharedMemorySize,
                                         dyn);
    if (e != cudaSuccess) {
        (void)cudaGetLastError();
        ncache = 25;
        dyn    = base + 25 * ROW_U4 * (int)sizeof(uint4);
        e = cudaFuncSetAttribute(gru_persistent,
                                 cudaFuncAttributeMaxDynamicSharedMemorySize,
                                 dyn);
        if (e != cudaSuccess) {
            (void)cudaGetLastError();
            ncache = 0;
            dyn    = base;
        }
    }

    gru_persistent<<<GRID, BLOCK, dyn>>>(x_seq,
                                         uwx, ub,
                                         rwx, rb,
                                         wx,  bb,
                                         v,   cc,
                                         (float*)d_out, horizon, ncache);
}

// round 10
// speedup vs baseline: 1.0811x; 1.0811x over previous
#include <cuda_runtime.h>
#include <cuda_fp16.h>
#include <cstdint>

#define H        4096
#define T_TRAIN  2048
#define GRID     148
#define BLOCK    1024         // 28 dot warps + 4 stager warps
#define DOTW     28
#define HMAX     64
#define NCACHE   26           // U-matrix rows cached in SMEM per CTA (big path)
#define ROW_U4   512          // uint4 per weight row (4096 halves = 8 KB)
#define DPAD     8            // ints per g_done slot (32B padding)

// ---------------- persistent device state ----------------------------------
__device__ __half   g_wu[(size_t)H * H];   // fp16 weights, PERMUTED layout:
__device__ __half   g_wr[(size_t)H * H];   // chunk j = cols {4j..4j+3, 2048+4j..2048+4j+3}
__device__ __half   g_wc[(size_t)H * H];
__device__ float    g_h[2][H];
__device__ float    g_vhp[HMAX + 1][GRID];
__device__ int      g_done[GRID * DPAD];   // per-CTA step-completion flags

// ---------------- fp32 -> fp16 conversion with column permutation -----------
__global__ void convert_w(const float* __restrict__ u,
                          const float* __restrict__ r,
                          const float* __restrict__ c)
{
    const int total = H * ROW_U4;
    int idx = blockIdx.x * blockDim.x + threadIdx.x;
    if (idx >= total) return;
    const int row = idx >> 9;
    const int j   = idx & 511;
    const int i0  = row * (H / 4) + j;        // float4 index of cols 4j..4j+3
    const int i1  = i0 + 512;                 // float4 index of cols 2048+4j..+3

    #define CVT_ONE(SRC, DST)                                           \
    {                                                                   \
        float4 a = ((const float4*)SRC)[i0];                            \
        float4 b = ((const float4*)SRC)[i1];                            \
        uint4 o;                                                        \
        __half2 t;                                                      \
        t = __floats2half2_rn(a.x, a.y); o.x = *(unsigned*)&t;          \
        t = __floats2half2_rn(a.z, a.w); o.y = *(unsigned*)&t;          \
        t = __floats2half2_rn(b.x, b.y); o.z = *(unsigned*)&t;          \
        t = __floats2half2_rn(b.z, b.w); o.w = *(unsigned*)&t;          \
        ((uint4*)DST)[idx] = o;                                         \
    }
    CVT_ONE(u, g_wu)
    CVT_ONE(r, g_wr)
    CVT_ONE(c, g_wc)
    #undef CVT_ONE
}

__device__ __forceinline__ float sigmoidf_fast(float z) {
    return 1.0f / (1.0f + __expf(-z));
}

// packed f32x2 fma: acc(lo,hi) += (x0,x1) * (y0,y1); acc carried as u64
__device__ __forceinline__ void ffma2(unsigned long long& acc,
                                      float x0, float x1,
                                      float y0, float y1)
{
    unsigned long long a, b;
    asm("mov.b64 %0, {%1, %2};" : "=l"(a) : "f"(x0), "f"(x1));
    asm("mov.b64 %0, {%1, %2};" : "=l"(b) : "f"(y0), "f"(y1));
    asm("fma.rn.f32x2 %0, %1, %2, %3;" : "=l"(acc) : "l"(a), "l"(b), "l"(acc));
}

__device__ __forceinline__ float hsum2(unsigned long long acc) {
    float lo, hi;
    asm("mov.b64 {%0, %1}, %2;" : "=f"(lo), "=f"(hi) : "l"(acc));
    return lo + hi;
}

// 8 fp16 weights (one uint4, permuted) x matching 8 h values -> packed acc
__device__ __forceinline__ void acc8p(uint4 w, float4 ha, float4 hb,
                                      unsigned long long& acc)
{
    float2 f0 = __half22float2(*(__half2*)&w.x);
    float2 f1 = __half22float2(*(__half2*)&w.y);
    float2 f2 = __half22float2(*(__half2*)&w.z);
    float2 f3 = __half22float2(*(__half2*)&w.w);
    ffma2(acc, f0.x, f0.y, ha.x, ha.y);
    ffma2(acc, f1.x, f1.y, ha.z, ha.w);
    ffma2(acc, f2.x, f2.y, hb.x, hb.y);
    ffma2(acc, f3.x, f3.y, hb.z, hb.w);
}

// spin on 4 per-stager-warp step flags (values are monotone step numbers)
__device__ __forceinline__ void wait_flags(volatile int* f, int t) {
    while (f[0] < t || f[1] < t || f[2] < t || f[3] < t) { }
}

// 8 dot batches (j = lane + 32k, k in [k0, k0+8)), depth-1 weight prefetch
// (R8-proven structure, unchanged)
__device__ __forceinline__ void dot3_half(const uint4* pu, const uint4* pr,
                                          const uint4* pc, const float4* h4,
                                          int lane, int k0,
                                          unsigned long long& au,
                                          unsigned long long& ar,
                                          unsigned long long& ac)
{
    int j = lane + 32 * k0;
    uint4 wu = pu[j], wr = pr[j], wc = pc[j];
    #pragma unroll 7
    for (int k = 0; k < 7; ++k) {
        const int jn = j + 32;
        uint4 nu = pu[jn], nr = pr[jn], nc = pc[jn];
        float4 ha = h4[j];         // stride 16B -> conflict-free
        float4 hb = h4[512 + j];   // stride 16B -> conflict-free
        acc8p(wu, ha, hb, au);
        acc8p(wr, ha, hb, ar);
        acc8p(wc, ha, hb, ac);
        wu = nu; wr = nr; wc = nc; j = jn;
    }
    float4 ha = h4[j];
    float4 hb = h4[512 + j];
    acc8p(wu, ha, hb, au);
    acc8p(wr, ha, hb, ar);
    acc8p(wc, ha, hb, ac);
}

// ---------------- persistent GRU kernel -------------------------------------
__global__ void __launch_bounds__(BLOCK, 1)
gru_persistent(const float* __restrict__ x_seq,
               const float* __restrict__ uwx, const float* __restrict__ ub,
               const float* __restrict__ rwx, const float* __restrict__ rb,
               const float* __restrict__ wx,  const float* __restrict__ bb,
               const float* __restrict__ v,   const float* __restrict__ cc,
               float* __restrict__ out, int horizon, int ncache)
{
    extern __shared__ char smem[];
    float* h_s = (float*)smem;                         // 16 KB
    uint4* ws  = (uint4*)(smem + H * sizeof(float));   // ncache rows of U

    __shared__ float au_s[32], ar_s[32], aw_s[32];
    __shared__ float x_s;
    __shared__ int   flA[4], flB[4];                   // per-stager-warp flags

    const int tid  = threadIdx.x;
    const int b    = blockIdx.x;
    const int G    = gridDim.x;
    const int warp = tid >> 5;
    const int lane = tid & 31;

    const int r0 = (int)(((long long)b       * H) / G);
    const int r1 = (int)(((long long)(b + 1) * H) / G);
    const int nrows = r1 - r0;   // 27 or 28 (<= DOTW)

    if (tid < 4) { flA[tid] = -1; flB[tid] = -1; }

    // per-row gate constants: lane L of warp 0 owns row r0+L
    float p_uwx = 0.f, p_ub = 0.f, p_rwx = 0.f, p_rb = 0.f;
    float p_wx = 0.f, p_bb = 0.f, p_v = 0.f;
    if (warp == 0 && lane < nrows) {
        const int row = r0 + lane;
        p_uwx = uwx[row]; p_ub = ub[row];
        p_rwx = rwx[row]; p_rb = rb[row];
        p_wx  = wx[row];  p_bb = bb[row];
        p_v   = v[row];
    }

    // prologue: pin first `ncache` U-rows of this CTA into SMEM
    {
        const uint4* src = ((const uint4*)g_wu) + (size_t)r0 * ROW_U4;
        const int n = ncache * ROW_U4;
        for (int i = tid; i < n; i += BLOCK) ws[i] = src[i];
    }

    // matvec row pointers (warp w owns row r0+w for all three matrices)
    const bool mv_active = (warp < nrows);
    const uint4* pu = nullptr; const uint4* pr = nullptr; const uint4* pc = nullptr;
    if (mv_active) {
        const size_t off = (size_t)(r0 + warp) * ROW_U4;
        pu = (warp < ncache) ? (ws + (size_t)warp * ROW_U4)
                             : (((const uint4*)g_wu) + off);
        pr = ((const uint4*)g_wr) + off;
        pc = ((const uint4*)g_wc) + off;
    }

    const float c0 = cc[0];
    const int total_steps = T_TRAIN + horizon;
    __syncthreads();   // flags init + ws cache visible to all warps

    for (int t = 0; t < total_steps; ++t) {
        const int par = t & 1;
        const float* hin  = g_h[par];
        float*       hout = g_h[par ^ 1];

        if (warp >= DOTW) {
            // ---- stager warps ----
            const int sw  = warp - DOTW;        // 0..3
            const int sid = tid - DOTW * 32;    // 0..127

            // distributed barrier wait: all CTAs done with step t-1
            {
                volatile int* gd = g_done;
                const int s0 = sid * DPAD;
                const int s1 = (sid + 128) * DPAD;
                if (sid + 128 < GRID) {
                    while (gd[s0] < t - 1 || gd[s1] < t - 1) { }
                } else {
                    while (gd[s0] < t - 1) { }
                }
            }
            asm volatile("bar.sync 1, 128;" ::: "memory");  // stager handshake
            __threadfence();                                 // acquire before h reads

            const float4* src = (const float4*)hin;
            float4*       dst = (float4*)h_s;
            // chunk A: f4 [0,256) and [512,768)  (dot batches k<8)
            #pragma unroll
            for (int i = sid; i < 256; i += 128) {
                dst[i]       = src[i];
                dst[512 + i] = src[512 + i];
            }
            __syncwarp();
            __threadfence_block();
            if (lane == 0) flA[sw] = t;
            // chunk B: f4 [256,512) and [768,1024)  (dot batches k>=8)
            #pragma unroll
            for (int i = sid; i < 256; i += 128) {
                dst[256 + i] = src[256 + i];
                dst[768 + i] = src[768 + i];
            }
            __syncwarp();
            __threadfence_block();
            if (lane == 0) flB[sw] = t;

            // warp 31 additionally computes x for this step (hidden latency)
            if (warp == 31) {
                if (t < T_TRAIN) {
                    if (lane == 0) x_s = x_seq[t];
                } else {
                    const float* p = g_vhp[t - T_TRAIN];
                    float s = 0.f;
                    for (int i = lane; i < G; i += 32) s += p[i];
                    #pragma unroll
                    for (int o = 16; o; o >>= 1)
                        s += __shfl_down_sync(0xffffffffu, s, o);
                    if (lane == 0) x_s = s + c0;
                }
            }
        } else if (mv_active) {
            // ---- dot warps: fused 3-matrix row-dot, flag-gated on h chunks ----
            const float4* h4 = (const float4*)h_s;
            unsigned long long au = 0ull, ar = 0ull, ac = 0ull;
            wait_flags(flA, t);
            dot3_half(pu, pr, pc, h4, lane, 0, au, ar, ac);
            wait_flags(flB, t);
            dot3_half(pu, pr, pc, h4, lane, 8, au, ar, ac);

            float su = hsum2(au), sr = hsum2(ar), sc = hsum2(ac);
            #pragma unroll
            for (int o = 16; o; o >>= 1) {
                su += __shfl_down_sync(0xffffffffu, su, o);
                sr += __shfl_down_sync(0xffffffffu, sr, o);
                sc += __shfl_down_sync(0xffffffffu, sc, o);
            }
            if (lane == 0) { au_s[warp] = su; ar_s[warp] = sr; aw_s[warp] = sc; }
        }
        __syncthreads();   // dots + x_s + full h_s ready

        // gate math + h update + y partial: warp 0
        const bool need_y = (t >= T_TRAIN - 1);
        if (warp == 0) {
            const float x = x_s;
            float yv = 0.f;
            if (lane < nrows) {
                const int row = r0 + lane;
                const float h_old = h_s[row];
                const float u  = sigmoidf_fast(p_uwx * x + au_s[lane] + p_ub);
                const float r  = sigmoidf_fast(p_rwx * x + ar_s[lane] + p_rb);
                const float hh = tanhf(p_wx * x + r * aw_s[lane] + p_bb);
                const float hn = h_old + u * (hh - h_old);
                hout[row] = hn;
                yv = need_y ? p_v * hn : 0.f;
            }
            if (need_y) {
                #pragma unroll
                for (int o = 16; o; o >>= 1)
                    yv += __shfl_down_sync(0xffffffffu, yv, o);
                if (lane == 0) g_vhp[t - (T_TRAIN - 1)][b] = yv;
            }
            __threadfence();   // release h/y writes before completion flag
        }
        __syncthreads();       // all writes fenced before tid 0 signals
        if (tid == 0) {
            *(volatile int*)&g_done[b * DPAD] = t;
        }
    }

    // final barrier: CTA 0 must see every CTA's last step before the epilogue
    if (b == 0) {
        if (tid < G) {
            volatile int* gd = g_done;
            while (gd[tid * DPAD] < total_steps - 1) { }
        }
        __syncthreads();
        __threadfence();
        if (tid < horizon) {
            const float* p = g_vhp[tid + 1];
            float s = 0.f;
            for (int i = 0; i < G; ++i) s += p[i];
            out[tid] = s + c0;
        }
    }
}

// ---------------- launch ----------------------------------------------------
extern "C" void kernel_launch(void* const* d_in, const int* in_sizes, int n_in,
                              void* d_out, int out_size)
{
    (void)in_sizes; (void)n_in;
    const float* x_seq = (const float*)d_in[0];
    // d_in[1] is the scalar 'horizon' (int32); we use out_size instead.
    const float* uwx = (const float*)d_in[2];
    const float* uWh = (const float*)d_in[3];
    const float* ub  = (const float*)d_in[4];
    const float* rwx = (const float*)d_in[5];
    const float* rWh = (const float*)d_in[6];
    const float* rb  = (const float*)d_in[7];
    const float* wx  = (const float*)d_in[8];
    const float* Wh  = (const float*)d_in[9];
    const float* bb  = (const float*)d_in[10];
    const float* v   = (const float*)d_in[11];
    const float* cc  = (const float*)d_in[12];

    int horizon = out_size;
    if (horizon > HMAX) horizon = HMAX;

    // reset persistent state (graph-capturable, deterministic per replay)
    void* p;
    cudaGetSymbolAddress(&p, g_h);    cudaMemsetAsync(p, 0, sizeof(float) * 2 * H);
    cudaGetSymbolAddress(&p, g_done); cudaMemsetAsync(p, 0xFF, sizeof(int) * GRID * DPAD);

    // fp32 -> fp16 permuted weight conversion
    {
        const int total = H * ROW_U4;
        convert_w<<<(total + 255) / 256, 256>>>(uWh, rWh, Wh);
    }

    // dyn-smem: try 26-row cache, then 25, then none (same decision every call)
    const int base = H * (int)sizeof(float);
    int ncache = NCACHE;
    int dyn    = base + NCACHE * ROW_U4 * (int)sizeof(uint4);
    cudaError_t e = cudaFuncSetAttribute(gru_persistent,
                                         cudaFuncAttributeMaxDynamicSharedMemorySize,
                                         dyn);
    if (e != cudaSuccess) {
        (void)cudaGetLastError();
        ncache = 25;
        dyn    = base + 25 * ROW_U4 * (int)sizeof(uint4);
        e = cudaFuncSetAttribute(gru_persistent,
                                 cudaFuncAttributeMaxDynamicSharedMemorySize,
                                 dyn);
        if (e != cudaSuccess) {
            (void)cudaGetLastError();
            ncache = 0;
            dyn    = base;
        }
    }

    gru_persistent<<<GRID, BLOCK, dyn>>>(x_seq,
                                         uwx, ub,
                                         rwx, rb,
                                         wx,  bb,
                                         v,   cc,
                                         (float*)d_out, horizon, ncache);
}

// round 11
// speedup vs baseline: 1.2421x; 1.1490x over previous
#include <cuda_runtime.h>
#include <cuda_fp16.h>
#include <cstdint>

#define H        4096
#define T_TRAIN  2048
#define GRID     148
#define BLOCK    1024         // 28 dot warps + 4 stager warps
#define DOTW     28
#define HMAX     64
#define NCACHE   26           // U-matrix rows cached in SMEM per CTA (big path)
#define ROW_U4   512          // uint4 per weight row (4096 halves = 8 KB)

// ---------------- persistent device state ----------------------------------
__device__ __half   g_wu[(size_t)H * H];   // fp16 weights, PERMUTED layout:
__device__ __half   g_wr[(size_t)H * H];   // chunk j = cols {4j..4j+3, 2048+4j..2048+4j+3}
__device__ __half   g_wc[(size_t)H * H];
__device__ float    g_h[2][H];
__device__ float    g_vhp[HMAX + 1][GRID];
__device__ unsigned g_count;               // centralized barrier (R8-proven)
__device__ unsigned g_phase;

// ---------------- fp32 -> fp16 conversion with column permutation -----------
__global__ void convert_w(const float* __restrict__ u,
                          const float* __restrict__ r,
                          const float* __restrict__ c)
{
    const int total = H * ROW_U4;
    int idx = blockIdx.x * blockDim.x + threadIdx.x;
    if (idx >= total) return;
    const int row = idx >> 9;
    const int j   = idx & 511;
    const int i0  = row * (H / 4) + j;        // float4 index of cols 4j..4j+3
    const int i1  = i0 + 512;                 // float4 index of cols 2048+4j..+3

    #define CVT_ONE(SRC, DST)                                           \
    {                                                                   \
        float4 a = ((const float4*)SRC)[i0];                            \
        float4 b = ((const float4*)SRC)[i1];                            \
        uint4 o;                                                        \
        __half2 t;                                                      \
        t = __floats2half2_rn(a.x, a.y); o.x = *(unsigned*)&t;          \
        t = __floats2half2_rn(a.z, a.w); o.y = *(unsigned*)&t;          \
        t = __floats2half2_rn(b.x, b.y); o.z = *(unsigned*)&t;          \
        t = __floats2half2_rn(b.z, b.w); o.w = *(unsigned*)&t;          \
        ((uint4*)DST)[idx] = o;                                         \
    }
    CVT_ONE(u, g_wu)
    CVT_ONE(r, g_wr)
    CVT_ONE(c, g_wc)
    #undef CVT_ONE
}

// ---------------- grid-wide barrier (R8-proven centralized version) ----------
__device__ __forceinline__ void grid_barrier(unsigned &local_phase, int G) {
    __threadfence();
    __syncthreads();
    if (threadIdx.x == 0) {
        unsigned target = local_phase + 1;
        unsigned arrived = atomicAdd(&g_count, 1u) + 1;
        if (arrived == (unsigned)G) {
            atomicExch(&g_count, 0u);
            __threadfence();
            atomicAdd(&g_phase, 1u);
        } else {
            volatile unsigned* ph = &g_phase;
            while (*ph < target) { }
        }
    }
    local_phase++;
    __syncthreads();
    __threadfence();
}

__device__ __forceinline__ float sigmoidf_fast(float z) {
    return 1.0f / (1.0f + __expf(-z));
}

// packed f32x2 fma: acc(lo,hi) += (x0,x1) * (y0,y1); acc carried as u64
__device__ __forceinline__ void ffma2(unsigned long long& acc,
                                      float x0, float x1,
                                      float y0, float y1)
{
    unsigned long long a, b;
    asm("mov.b64 %0, {%1, %2};" : "=l"(a) : "f"(x0), "f"(x1));
    asm("mov.b64 %0, {%1, %2};" : "=l"(b) : "f"(y0), "f"(y1));
    asm("fma.rn.f32x2 %0, %1, %2, %3;" : "=l"(acc) : "l"(a), "l"(b), "l"(acc));
}

__device__ __forceinline__ float hsum2(unsigned long long acc) {
    float lo, hi;
    asm("mov.b64 {%0, %1}, %2;" : "=f"(lo), "=f"(hi) : "l"(acc));
    return lo + hi;
}

// 8 fp16 weights (one uint4, permuted) x matching 8 h values -> packed acc
__device__ __forceinline__ void acc8p(uint4 w, float4 ha, float4 hb,
                                      unsigned long long& acc)
{
    float2 f0 = __half22float2(*(__half2*)&w.x);
    float2 f1 = __half22float2(*(__half2*)&w.y);
    float2 f2 = __half22float2(*(__half2*)&w.z);
    float2 f3 = __half22float2(*(__half2*)&w.w);
    ffma2(acc, f0.x, f0.y, ha.x, ha.y);
    ffma2(acc, f1.x, f1.y, ha.z, ha.w);
    ffma2(acc, f2.x, f2.y, hb.x, hb.y);
    ffma2(acc, f3.x, f3.y, hb.z, hb.w);
}

// spin on 4 per-stager-warp step flags (values are monotone step numbers)
__device__ __forceinline__ void wait_flags(volatile int* f, int t) {
    while (f[0] < t || f[1] < t || f[2] < t || f[3] < t) { }
}

// 8 dot batches (j = lane + 32k, k in [k0, k0+8)):
// DEPTH-2 rolling weight prefetch, FULLY UNROLLED (compile-time indices).
// This is the single change vs R8 (which was depth-1).
__device__ __forceinline__ void dot3_half(const uint4* pu, const uint4* pr,
                                          const uint4* pc, const float4* h4,
                                          int lane, int k0,
                                          unsigned long long& au,
                                          unsigned long long& ar,
                                          unsigned long long& ac)
{
    const int base = lane + 32 * k0;
    uint4 wu0 = pu[base],      wr0 = pr[base],      wc0 = pc[base];
    uint4 wu1 = pu[base + 32], wr1 = pr[base + 32], wc1 = pc[base + 32];
    #pragma unroll
    for (int k = 0; k < 8; ++k) {
        const int j = base + 32 * k;          // compile-time offset after unroll
        uint4 nu, nr, nc;
        if (k < 6) {                           // folds away at compile time
            nu = pu[j + 64]; nr = pr[j + 64]; nc = pc[j + 64];
        }
        float4 ha = h4[j];         // stride 16B -> conflict-free
        float4 hb = h4[512 + j];   // stride 16B -> conflict-free
        acc8p(wu0, ha, hb, au);
        acc8p(wr0, ha, hb, ar);
        acc8p(wc0, ha, hb, ac);
        wu0 = wu1; wr0 = wr1; wc0 = wc1;
        if (k < 6) { wu1 = nu; wr1 = nr; wc1 = nc; }
    }
}

// ---------------- persistent GRU kernel -------------------------------------
__global__ void __launch_bounds__(BLOCK, 1)
gru_persistent(const float* __restrict__ x_seq,
               const float* __restrict__ uwx, const float* __restrict__ ub,
               const float* __restrict__ rwx, const float* __restrict__ rb,
               const float* __restrict__ wx,  const float* __restrict__ bb,
               const float* __restrict__ v,   const float* __restrict__ cc,
               float* __restrict__ out, int horizon, int ncache)
{
    extern __shared__ char smem[];
    float* h_s = (float*)smem;                         // 16 KB
    uint4* ws  = (uint4*)(smem + H * sizeof(float));   // ncache rows of U

    __shared__ float au_s[32], ar_s[32], aw_s[32];
    __shared__ float x_s;
    __shared__ int   flA[4], flB[4];                   // per-stager-warp flags

    const int tid  = threadIdx.x;
    const int b    = blockIdx.x;
    const int G    = gridDim.x;
    const int warp = tid >> 5;
    const int lane = tid & 31;

    const int r0 = (int)(((long long)b       * H) / G);
    const int r1 = (int)(((long long)(b + 1) * H) / G);
    const int nrows = r1 - r0;   // 27 or 28 (<= DOTW)

    if (tid < 4) { flA[tid] = -1; flB[tid] = -1; }

    // per-row gate constants: lane L of warp 0 owns row r0+L
    float p_uwx = 0.f, p_ub = 0.f, p_rwx = 0.f, p_rb = 0.f;
    float p_wx = 0.f, p_bb = 0.f, p_v = 0.f;
    if (warp == 0 && lane < nrows) {
        const int row = r0 + lane;
        p_uwx = uwx[row]; p_ub = ub[row];
        p_rwx = rwx[row]; p_rb = rb[row];
        p_wx  = wx[row];  p_bb = bb[row];
        p_v   = v[row];
    }

    // prologue: pin first `ncache` U-rows of this CTA into SMEM
    {
        const uint4* src = ((const uint4*)g_wu) + (size_t)r0 * ROW_U4;
        const int n = ncache * ROW_U4;
        for (int i = tid; i < n; i += BLOCK) ws[i] = src[i];
    }

    // matvec row pointers (warp w owns row r0+w for all three matrices)
    const bool mv_active = (warp < nrows);
    const uint4* pu = nullptr; const uint4* pr = nullptr; const uint4* pc = nullptr;
    if (mv_active) {
        const size_t off = (size_t)(r0 + warp) * ROW_U4;
        pu = (warp < ncache) ? (ws + (size_t)warp * ROW_U4)
                             : (((const uint4*)g_wu) + off);
        pr = ((const uint4*)g_wr) + off;
        pc = ((const uint4*)g_wc) + off;
    }

    const float c0 = cc[0];
    unsigned phase = 0;
    const int total_steps = T_TRAIN + horizon;
    __syncthreads();   // flags init + ws cache visible to all warps

    for (int t = 0; t < total_steps; ++t) {
        const int par = t & 1;
        const float* hin  = g_h[par];
        float*       hout = g_h[par ^ 1];

        if (warp >= DOTW) {
            // ---- stager warps: copy h in 2 chunks, publish step flags ----
            const int sw  = warp - DOTW;        // 0..3
            const int sid = tid - DOTW * 32;    // 0..127
            const float4* src = (const float4*)hin;
            float4*       dst = (float4*)h_s;
            // chunk A: f4 [0,256) and [512,768)  (dot batches k<8)
            #pragma unroll
            for (int i = sid; i < 256; i += 128) {
                dst[i]       = src[i];
                dst[512 + i] = src[512 + i];
            }
            __syncwarp();
            __threadfence_block();
            if (lane == 0) flA[sw] = t;
            // chunk B: f4 [256,512) and [768,1024)  (dot batches k>=8)
            #pragma unroll
            for (int i = sid; i < 256; i += 128) {
                dst[256 + i] = src[256 + i];
                dst[768 + i] = src[768 + i];
            }
            __syncwarp();
            __threadfence_block();
            if (lane == 0) flB[sw] = t;

            // warp 31 additionally computes x for this step (hidden latency)
            if (warp == 31) {
                if (t < T_TRAIN) {
                    if (lane == 0) x_s = x_seq[t];
                } else {
                    const float* p = g_vhp[t - T_TRAIN];
                    float s = 0.f;
                    for (int i = lane; i < G; i += 32) s += p[i];
                    #pragma unroll
                    for (int o = 16; o; o >>= 1)
                        s += __shfl_down_sync(0xffffffffu, s, o);
                    if (lane == 0) x_s = s + c0;
                }
            }
        } else if (mv_active) {
            // ---- dot warps: fused 3-matrix row-dot, flag-gated on h chunks ----
            const float4* h4 = (const float4*)h_s;
            unsigned long long au = 0ull, ar = 0ull, ac = 0ull;
            wait_flags(flA, t);
            dot3_half(pu, pr, pc, h4, lane, 0, au, ar, ac);
            wait_flags(flB, t);
            dot3_half(pu, pr, pc, h4, lane, 8, au, ar, ac);

            float su = hsum2(au), sr = hsum2(ar), sc = hsum2(ac);
            #pragma unroll
            for (int o = 16; o; o >>= 1) {
                su += __shfl_down_sync(0xffffffffu, su, o);
                sr += __shfl_down_sync(0xffffffffu, sr, o);
                sc += __shfl_down_sync(0xffffffffu, sc, o);
            }
            if (lane == 0) { au_s[warp] = su; ar_s[warp] = sr; aw_s[warp] = sc; }
        }
        __syncthreads();   // dots + x_s + full h_s ready

        // gate math + h update + y partial: warp 0
        const bool need_y = (t >= T_TRAIN - 1);
        if (warp == 0) {
            const float x = x_s;
            float yv = 0.f;
            if (lane < nrows) {
                const int row = r0 + lane;
                const float h_old = h_s[row];
                const float u  = sigmoidf_fast(p_uwx * x + au_s[lane] + p_ub);
                const float r  = sigmoidf_fast(p_rwx * x + ar_s[lane] + p_rb);
                const float hh = tanhf(p_wx * x + r * aw_s[lane] + p_bb);
                const float hn = h_old + u * (hh - h_old);
                hout[row] = hn;
                yv = need_y ? p_v * hn : 0.f;
            }
            if (need_y) {
                #pragma unroll
                for (int o = 16; o; o >>= 1)
                    yv += __shfl_down_sync(0xffffffffu, yv, o);
                if (lane == 0) g_vhp[t - (T_TRAIN - 1)][b] = yv;
            }
        }

        grid_barrier(phase, G);
    }

    // emit predictions (deterministic final reduction)
    if (b == 0 && tid < horizon) {
        const float* p = g_vhp[tid + 1];
        float s = 0.f;
        for (int i = 0; i < G; ++i) s += p[i];
        out[tid] = s + c0;
    }
}

// ---------------- launch ----------------------------------------------------
extern "C" void kernel_launch(void* const* d_in, const int* in_sizes, int n_in,
                              void* d_out, int out_size)
{
    (void)in_sizes; (void)n_in;
    const float* x_seq = (const float*)d_in[0];
    // d_in[1] is the scalar 'horizon' (int32); we use out_size instead.
    const float* uwx = (const float*)d_in[2];
    const float* uWh = (const float*)d_in[3];
    const float* ub  = (const float*)d_in[4];
    const float* rwx = (const float*)d_in[5];
    const float* rWh = (const float*)d_in[6];
    const float* rb  = (const float*)d_in[7];
    const float* wx  = (const float*)d_in[8];
    const float* Wh  = (const float*)d_in[9];
    const float* bb  = (const float*)d_in[10];
    const float* v   = (const float*)d_in[11];
    const float* cc  = (const float*)d_in[12];

    int horizon = out_size;
    if (horizon > HMAX) horizon = HMAX;

    // reset persistent state (graph-capturable, deterministic per replay)
    void* p;
    cudaGetSymbolAddress(&p, g_h);     cudaMemsetAsync(p, 0, sizeof(float) * 2 * H);
    cudaGetSymbolAddress(&p, g_count); cudaMemsetAsync(p, 0, sizeof(unsigned));
    cudaGetSymbolAddress(&p, g_phase); cudaMemsetAsync(p, 0, sizeof(unsigned));

    // fp32 -> fp16 permuted weight conversion
    {
        const int total = H * ROW_U4;
        convert_w<<<(total + 255) / 256, 256>>>(uWh, rWh, Wh);
    }

    // dyn-smem: try 26-row cache, then 25, then none (same decision every call)
    const int base = H * (int)sizeof(float);
    int ncache = NCACHE;
    int dyn    = base + NCACHE * ROW_U4 * (int)sizeof(uint4);
    cudaError_t e = cudaFuncSetAttribute(gru_persistent,
                                         cudaFuncAttributeMaxDynamicSharedMemorySize,
                                         dyn);
    if (e != cudaSuccess) {
        (void)cudaGetLastError();
        ncache = 25;
        dyn    = base + 25 * ROW_U4 * (int)sizeof(uint4);
        e = cudaFuncSetAttribute(gru_persistent,
                                 cudaFuncAttributeMaxDynamicSharedMemorySize,
                                 dyn);
        if (e != cudaSuccess) {
            (void)cudaGetLastError();
            ncache = 0;
            dyn    = base;
        }
    }

    gru_persistent<<<GRID, BLOCK, dyn>>>(x_seq,
                                         uwx, ub,
                                         rwx, rb,
                                         wx,  bb,
                                         v,   cc,
                                         (float*)d_out, horizon, ncache);
}

// round 12
// speedup vs baseline: 1.2575x; 1.0124x over previous
#include <cuda_runtime.h>
#include <cuda_fp16.h>
#include <cstdint>

#define H        4096
#define T_TRAIN  2048
#define GRID     148
#define BLOCK    1024         // 28 dot warps + 4 stager warps
#define DOTW     28
#define HMAX     64
#define NCACHE   26           // U-matrix rows cached in SMEM per CTA (big path)
#define ROW_U4   512          // uint4 per weight row (4096 halves = 8 KB)

// ---------------- persistent device state ----------------------------------
__device__ __half   g_wu[(size_t)H * H];   // fp16 weights, PERMUTED layout:
__device__ __half   g_wr[(size_t)H * H];   // chunk j = cols {4j..4j+3, 2048+4j..2048+4j+3}
__device__ __half   g_wc[(size_t)H * H];
__device__ float    g_h[2][H];
__device__ float    g_vhp[HMAX + 1][GRID];
__device__ unsigned g_count;               // centralized barrier (R8-proven)
__device__ unsigned g_phase;

// ---------------- fp32 -> fp16 conversion with column permutation -----------
__global__ void convert_w(const float* __restrict__ u,
                          const float* __restrict__ r,
                          const float* __restrict__ c)
{
    const int total = H * ROW_U4;
    int idx = blockIdx.x * blockDim.x + threadIdx.x;
    if (idx >= total) return;
    const int row = idx >> 9;
    const int j   = idx & 511;
    const int i0  = row * (H / 4) + j;        // float4 index of cols 4j..4j+3
    const int i1  = i0 + 512;                 // float4 index of cols 2048+4j..+3

    #define CVT_ONE(SRC, DST)                                           \
    {                                                                   \
        float4 a = ((const float4*)SRC)[i0];                            \
        float4 b = ((const float4*)SRC)[i1];                            \
        uint4 o;                                                        \
        __half2 t;                                                      \
        t = __floats2half2_rn(a.x, a.y); o.x = *(unsigned*)&t;          \
        t = __floats2half2_rn(a.z, a.w); o.y = *(unsigned*)&t;          \
        t = __floats2half2_rn(b.x, b.y); o.z = *(unsigned*)&t;          \
        t = __floats2half2_rn(b.z, b.w); o.w = *(unsigned*)&t;          \
        ((uint4*)DST)[idx] = o;                                         \
    }
    CVT_ONE(u, g_wu)
    CVT_ONE(r, g_wr)
    CVT_ONE(c, g_wc)
    #undef CVT_ONE
}

// ---------------- grid-wide barrier (R8-proven centralized version) ----------
__device__ __forceinline__ void grid_barrier(unsigned &local_phase, int G) {
    __threadfence();
    __syncthreads();
    if (threadIdx.x == 0) {
        unsigned target = local_phase + 1;
        unsigned arrived = atomicAdd(&g_count, 1u) + 1;
        if (arrived == (unsigned)G) {
            atomicExch(&g_count, 0u);
            __threadfence();
            atomicAdd(&g_phase, 1u);
        } else {
            volatile unsigned* ph = &g_phase;
            while (*ph < target) { }
        }
    }
    local_phase++;
    __syncthreads();
    __threadfence();
}

__device__ __forceinline__ float sigmoidf_fast(float z) {
    return 1.0f / (1.0f + __expf(-z));
}

// packed f32x2 fma: acc(lo,hi) += (x0,x1) * (y0,y1); acc carried as u64
__device__ __forceinline__ void ffma2(unsigned long long& acc,
                                      float x0, float x1,
                                      float y0, float y1)
{
    unsigned long long a, b;
    asm("mov.b64 %0, {%1, %2};" : "=l"(a) : "f"(x0), "f"(x1));
    asm("mov.b64 %0, {%1, %2};" : "=l"(b) : "f"(y0), "f"(y1));
    asm("fma.rn.f32x2 %0, %1, %2, %3;" : "=l"(acc) : "l"(a), "l"(b), "l"(acc));
}

__device__ __forceinline__ float hsum2(unsigned long long acc) {
    float lo, hi;
    asm("mov.b64 {%0, %1}, %2;" : "=f"(lo), "=f"(hi) : "l"(acc));
    return lo + hi;
}

// 8 fp16 weights (one uint4, permuted) x matching 8 h values -> packed acc
__device__ __forceinline__ void acc8p(uint4 w, float4 ha, float4 hb,
                                      unsigned long long& acc)
{
    float2 f0 = __half22float2(*(__half2*)&w.x);
    float2 f1 = __half22float2(*(__half2*)&w.y);
    float2 f2 = __half22float2(*(__half2*)&w.z);
    float2 f3 = __half22float2(*(__half2*)&w.w);
    ffma2(acc, f0.x, f0.y, ha.x, ha.y);
    ffma2(acc, f1.x, f1.y, ha.z, ha.w);
    ffma2(acc, f2.x, f2.y, hb.x, hb.y);
    ffma2(acc, f3.x, f3.y, hb.z, hb.w);
}

// spin on 4 per-stager-warp step flags (values are monotone step numbers)
__device__ __forceinline__ void wait_flags(volatile int* f, int t) {
    while (f[0] < t || f[1] < t || f[2] < t || f[3] < t) { }
}

// ---------------- persistent GRU kernel -------------------------------------
__global__ void __launch_bounds__(BLOCK, 1)
gru_persistent(const float* __restrict__ x_seq,
               const float* __restrict__ uwx, const float* __restrict__ ub,
               const float* __restrict__ rwx, const float* __restrict__ rb,
               const float* __restrict__ wx,  const float* __restrict__ bb,
               const float* __restrict__ v,   const float* __restrict__ cc,
               float* __restrict__ out, int horizon, int ncache)
{
    extern __shared__ char smem[];
    float* h_s = (float*)smem;                         // 16 KB
    uint4* ws  = (uint4*)(smem + H * sizeof(float));   // ncache rows of U

    __shared__ float red_s[32];
    __shared__ float gc_s[7][DOTW];      // gate constants per owned row
    __shared__ float x_s;
    __shared__ int   flA[4], flB[4];     // per-stager-warp flags
    __shared__ int   flX;                // x-ready flag

    const int tid  = threadIdx.x;
    const int b    = blockIdx.x;
    const int G    = gridDim.x;
    const int warp = tid >> 5;
    const int lane = tid & 31;

    const int r0 = (int)(((long long)b       * H) / G);
    const int r1 = (int)(((long long)(b + 1) * H) / G);
    const int nrows = r1 - r0;   // 27 or 28 (<= DOTW)

    if (tid < 4) { flA[tid] = -1; flB[tid] = -1; }
    if (tid == 4) flX = -1;
    if (tid < 32) red_s[tid] = 0.f;
    // stage gate constants into SMEM (row r0+i -> column i)
    if (tid < nrows) {
        const int row = r0 + tid;
        gc_s[0][tid] = uwx[row]; gc_s[1][tid] = ub[row];
        gc_s[2][tid] = rwx[row]; gc_s[3][tid] = rb[row];
        gc_s[4][tid] = wx[row];  gc_s[5][tid] = bb[row];
        gc_s[6][tid] = v[row];
    }

    // prologue: pin first `ncache` U-rows of this CTA into SMEM
    {
        const uint4* src = ((const uint4*)g_wu) + (size_t)r0 * ROW_U4;
        const int n = ncache * ROW_U4;
        for (int i = tid; i < n; i += BLOCK) ws[i] = src[i];
    }

    // matvec row pointers (warp w owns row r0+w for all three matrices)
    const bool mv_active = (warp < nrows);
    const int  myrow = r0 + warp;
    const uint4* pu = nullptr; const uint4* pr = nullptr; const uint4* pc = nullptr;
    if (mv_active) {
        const size_t off = (size_t)myrow * ROW_U4;
        pu = (warp < ncache) ? (ws + (size_t)warp * ROW_U4)
                             : (((const uint4*)g_wu) + off);
        pr = ((const uint4*)g_wr) + off;
        pc = ((const uint4*)g_wc) + off;
    }

    const float c0 = cc[0];
    unsigned phase = 0;
    const int total_steps = T_TRAIN + horizon;
    __syncthreads();   // flags/constants/ws visible to all warps

    for (int t = 0; t < total_steps; ++t) {
        const int par = t & 1;
        const float* hin  = g_h[par];
        float*       hout = g_h[par ^ 1];
        const bool need_y = (t >= T_TRAIN - 1);

        if (warp >= DOTW) {
            // ---- stager warps ----
            const int sw  = warp - DOTW;        // 0..3
            const int sid = tid - DOTW * 32;    // 0..127

            // warp 31: publish x FIRST so dot warps never wait at the tail
            if (warp == 31) {
                if (t < T_TRAIN) {
                    if (lane == 0) {
                        x_s = x_seq[t];
                        __threadfence_block();
                        flX = t;
                    }
                } else {
                    const float* p = g_vhp[t - T_TRAIN];
                    float s = 0.f;
                    for (int i = lane; i < G; i += 32) s += p[i];
                    #pragma unroll
                    for (int o = 16; o; o >>= 1)
                        s += __shfl_down_sync(0xffffffffu, s, o);
                    if (lane == 0) {
                        x_s = s + c0;
                        __threadfence_block();
                        flX = t;
                    }
                }
            }

            const float4* src = (const float4*)hin;
            float4*       dst = (float4*)h_s;
            // chunk A: f4 [0,256) and [512,768)  (dot batches k<8)
            #pragma unroll
            for (int i = sid; i < 256; i += 128) {
                dst[i]       = src[i];
                dst[512 + i] = src[512 + i];
            }
            __syncwarp();
            __threadfence_block();
            if (lane == 0) flA[sw] = t;
            // chunk B: f4 [256,512) and [768,1024)  (dot batches k>=8)
            #pragma unroll
            for (int i = sid; i < 256; i += 128) {
                dst[256 + i] = src[256 + i];
                dst[768 + i] = src[768 + i];
            }
            __syncwarp();
            __threadfence_block();
            if (lane == 0) flB[sw] = t;
        } else if (mv_active) {
            // ---- dot warps: merged 16-batch loop, fully unrolled;
            //      first weights in flight BEFORE the flA wait;
            //      flB wait placed after batch-8 weights are in flight ----
            const float4* h4 = (const float4*)h_s;
            unsigned long long au = 0ull, ar = 0ull, ac = 0ull;

            uint4 wu0 = pu[lane], wr0 = pr[lane], wc0 = pc[lane];  // pre-wait
            wait_flags(flA, t);
            #pragma unroll
            for (int k = 0; k < 16; ++k) {
                const int j = lane + 32 * k;   // compile-time offset after unroll
                uint4 nu, nr, nc;
                if (k < 15) {                  // folds away (full unroll)
                    nu = pu[j + 32]; nr = pr[j + 32]; nc = pc[j + 32];
                }
                if (k == 8) wait_flags(flB, t);   // batch-8 weights already in flight
                float4 ha = h4[j];         // stride 16B -> conflict-free
                float4 hb = h4[512 + j];   // stride 16B -> conflict-free
                acc8p(wu0, ha, hb, au);
                acc8p(wr0, ha, hb, ar);
                acc8p(wc0, ha, hb, ac);
                if (k < 15) { wu0 = nu; wr0 = nr; wc0 = nc; }
            }

            float su = hsum2(au), sr = hsum2(ar), sc = hsum2(ac);
            #pragma unroll
            for (int o = 16; o; o >>= 1) {
                su += __shfl_down_sync(0xffffffffu, su, o);
                sr += __shfl_down_sync(0xffffffffu, sr, o);
                sc += __shfl_down_sync(0xffffffffu, sc, o);
            }

            // decentralized gate: lane 0 updates its own row
            if (lane == 0) {
                volatile int* fx = &flX;
                while (*fx < t) { }            // long since set; ~1 LDS
                const float x = x_s;
                const float h_old = h_s[myrow];
                const float u  = sigmoidf_fast(gc_s[0][warp] * x + su + gc_s[1][warp]);
                const float r  = sigmoidf_fast(gc_s[2][warp] * x + sr + gc_s[3][warp]);
                const float hh = tanhf(gc_s[4][warp] * x + r * sc + gc_s[5][warp]);
                const float hn = h_old + u * (hh - h_old);
                hout[myrow] = hn;
                if (need_y) red_s[warp] = gc_s[6][warp] * hn;
            }
        }

        // y partial reduction only on the last horizon+1 steps
        if (need_y) {
            __syncthreads();
            if (warp == 0) {
                float yv = (lane < nrows) ? red_s[lane] : 0.f;
                #pragma unroll
                for (int o = 16; o; o >>= 1)
                    yv += __shfl_down_sync(0xffffffffu, yv, o);
                if (lane == 0) g_vhp[t - (T_TRAIN - 1)][b] = yv;
            }
        }

        grid_barrier(phase, G);
    }

    // emit predictions (deterministic final reduction)
    if (b == 0 && tid < horizon) {
        const float* p = g_vhp[tid + 1];
        float s = 0.f;
        for (int i = 0; i < G; ++i) s += p[i];
        out[tid] = s + c0;
    }
}

// ---------------- launch ----------------------------------------------------
extern "C" void kernel_launch(void* const* d_in, const int* in_sizes, int n_in,
                              void* d_out, int out_size)
{
    (void)in_sizes; (void)n_in;
    const float* x_seq = (const float*)d_in[0];
    // d_in[1] is the scalar 'horizon' (int32); we use out_size instead.
    const float* uwx = (const float*)d_in[2];
    const float* uWh = (const float*)d_in[3];
    const float* ub  = (const float*)d_in[4];
    const float* rwx = (const float*)d_in[5];
    const float* rWh = (const float*)d_in[6];
    const float* rb  = (const float*)d_in[7];
    const float* wx  = (const float*)d_in[8];
    const float* Wh  = (const float*)d_in[9];
    const float* bb  = (const float*)d_in[10];
    const float* v   = (const float*)d_in[11];
    const float* cc  = (const float*)d_in[12];

    int horizon = out_size;
    if (horizon > HMAX) horizon = HMAX;

    // reset persistent state (graph-capturable, deterministic per replay)
    void* p;
    cudaGetSymbolAddress(&p, g_h);     cudaMemsetAsync(p, 0, sizeof(float) * 2 * H);
    cudaGetSymbolAddress(&p, g_count); cudaMemsetAsync(p, 0, sizeof(unsigned));
    cudaGetSymbolAddress(&p, g_phase); cudaMemsetAsync(p, 0, sizeof(unsigned));

    // fp32 -> fp16 permuted weight conversion
    {
        const int total = H * ROW_U4;
        convert_w<<<(total + 255) / 256, 256>>>(uWh, rWh, Wh);
    }

    // dyn-smem: try 26-row cache, then 25, then none (same decision every call)
    const int base = H * (int)sizeof(float);
    int ncache = NCACHE;
    int dyn    = base + NCACHE * ROW_U4 * (int)sizeof(uint4);
    cudaError_t e = cudaFuncSetAttribute(gru_persistent,
                                         cudaFuncAttributeMaxDynamicSharedMemorySize,
                                         dyn);
    if (e != cudaSuccess) {
        (void)cudaGetLastError();
        ncache = 25;
        dyn    = base + 25 * ROW_U4 * (int)sizeof(uint4);
        e = cudaFuncSetAttribute(gru_persistent,
                                 cudaFuncAttributeMaxDynamicSharedMemorySize,
                                 dyn);
        if (e != cudaSuccess) {
            (void)cudaGetLastError();
            ncache = 0;
            dyn    = base;
        }
    }

    gru_persistent<<<GRID, BLOCK, dyn>>>(x_seq,
                                         uwx, ub,
                                         rwx, rb,
                                         wx,  bb,
                                         v,   cc,
                                         (float*)d_out, horizon, ncache);
}

// round 13
// speedup vs baseline: 1.3405x; 1.0660x over previous
#include <cuda_runtime.h>
#include <cuda_fp16.h>
#include <cstdint>

#define H        4096
#define T_TRAIN  2048
#define GRID     148
#define BLOCK    1024         // 28 dot warps + 4 stager warps
#define DOTW     28
#define HMAX     64
#define NCACHE   27           // U-matrix rows cached in SMEM per CTA (big path)
#define ROW_U4   512          // uint4 per weight row (4096 halves = 8 KB)
#define H2_U4    512          // uint4 of packed fp16 h (4096 halves = 8 KB)

// ---------------- persistent device state ----------------------------------
__device__ __half   g_wu[(size_t)H * H];   // fp16 weights, PERMUTED layout:
__device__ __half   g_wr[(size_t)H * H];   // chunk j = cols {4j..4j+3, 2048+4j..2048+4j+3}
__device__ __half   g_wc[(size_t)H * H];
__device__ float    g_h[2][H];             // fp32 hidden-state chain (accuracy-critical)
__device__ float    g_vhp[HMAX + 1][GRID];
__device__ unsigned g_count;               // centralized barrier (R8-proven)
__device__ unsigned g_phase;

// ---------------- fp32 -> fp16 conversion with column permutation -----------
__global__ void convert_w(const float* __restrict__ u,
                          const float* __restrict__ r,
                          const float* __restrict__ c)
{
    const int total = H * ROW_U4;
    int idx = blockIdx.x * blockDim.x + threadIdx.x;
    if (idx >= total) return;
    const int row = idx >> 9;
    const int j   = idx & 511;
    const int i0  = row * (H / 4) + j;        // float4 index of cols 4j..4j+3
    const int i1  = i0 + 512;                 // float4 index of cols 2048+4j..+3

    #define CVT_ONE(SRC, DST)                                           \
    {                                                                   \
        float4 a = ((const float4*)SRC)[i0];                            \
        float4 b = ((const float4*)SRC)[i1];                            \
        uint4 o;                                                        \
        __half2 t;                                                      \
        t = __floats2half2_rn(a.x, a.y); o.x = *(unsigned*)&t;          \
        t = __floats2half2_rn(a.z, a.w); o.y = *(unsigned*)&t;          \
        t = __floats2half2_rn(b.x, b.y); o.z = *(unsigned*)&t;          \
        t = __floats2half2_rn(b.z, b.w); o.w = *(unsigned*)&t;          \
        ((uint4*)DST)[idx] = o;                                         \
    }
    CVT_ONE(u, g_wu)
    CVT_ONE(r, g_wr)
    CVT_ONE(c, g_wc)
    #undef CVT_ONE
}

// ---------------- grid-wide barrier (R8-proven centralized version) ----------
__device__ __forceinline__ void grid_barrier(unsigned &local_phase, int G) {
    __threadfence();
    __syncthreads();
    if (threadIdx.x == 0) {
        unsigned target = local_phase + 1;
        unsigned arrived = atomicAdd(&g_count, 1u) + 1;
        if (arrived == (unsigned)G) {
            atomicExch(&g_count, 0u);
            __threadfence();
            atomicAdd(&g_phase, 1u);
        } else {
            volatile unsigned* ph = &g_phase;
            while (*ph < target) { }
        }
    }
    local_phase++;
    __syncthreads();
    __threadfence();
}

__device__ __forceinline__ float sigmoidf_fast(float z) {
    return 1.0f / (1.0f + __expf(-z));
}

// packed f32x2 add: acc(lo,hi) += (x0,x1); acc carried as u64
__device__ __forceinline__ void fadd2(unsigned long long& acc, float x0, float x1)
{
    unsigned long long a;
    asm("mov.b64 %0, {%1, %2};" : "=l"(a) : "f"(x0), "f"(x1));
    asm("add.rn.f32x2 %0, %1, %2;" : "=l"(acc) : "l"(acc), "l"(a));
}

__device__ __forceinline__ float hsum2(unsigned long long acc) {
    float lo, hi;
    asm("mov.b64 {%0, %1}, %2;" : "=f"(lo), "=f"(hi) : "l"(acc));
    return lo + hi;
}

__device__ __forceinline__ __half2 u2h2(unsigned v) { return *(__half2*)&v; }

// 8-element packed-half partial dot: (w uint4) . (h uint4) -> float2
// 4 HFMA2/HMUL2 in fp16, then one half2->float2 conversion.
__device__ __forceinline__ float2 dot8h(uint4 w, uint4 h)
{
    __half2 p = __hmul2(u2h2(w.x), u2h2(h.x));
    p = __hfma2(u2h2(w.y), u2h2(h.y), p);
    p = __hfma2(u2h2(w.z), u2h2(h.z), p);
    p = __hfma2(u2h2(w.w), u2h2(h.w), p);
    return __half22float2(p);
}

// spin on 4 per-stager-warp step flags (values are monotone step numbers)
__device__ __forceinline__ void wait_flags(volatile int* f, int t) {
    while (f[0] < t || f[1] < t || f[2] < t || f[3] < t) { }
}

// ---------------- persistent GRU kernel -------------------------------------
__global__ void __launch_bounds__(BLOCK, 1)
gru_persistent(const float* __restrict__ x_seq,
               const float* __restrict__ uwx, const float* __restrict__ ub,
               const float* __restrict__ rwx, const float* __restrict__ rb,
               const float* __restrict__ wx,  const float* __restrict__ bb,
               const float* __restrict__ v,   const float* __restrict__ cc,
               float* __restrict__ out, int horizon, int ncache)
{
    extern __shared__ char smem[];
    uint4* h2s = (uint4*)smem;                          // 8 KB packed fp16 h
    uint4* ws  = (uint4*)(smem + H2_U4 * sizeof(uint4)); // ncache rows of U

    __shared__ float red_s[32];
    __shared__ float gc_s[7][DOTW];      // gate constants per owned row
    __shared__ float x_s;
    __shared__ int   flA[4], flB[4];     // per-stager-warp flags
    __shared__ int   flX;                // x-ready flag

    const int tid  = threadIdx.x;
    const int b    = blockIdx.x;
    const int G    = gridDim.x;
    const int warp = tid >> 5;
    const int lane = tid & 31;

    const int r0 = (int)(((long long)b       * H) / G);
    const int r1 = (int)(((long long)(b + 1) * H) / G);
    const int nrows = r1 - r0;   // 27 or 28 (<= DOTW)

    if (tid < 4) { flA[tid] = -1; flB[tid] = -1; }
    if (tid == 4) flX = -1;
    if (tid < 32) red_s[tid] = 0.f;
    // stage gate constants into SMEM (row r0+i -> column i)
    if (tid < nrows) {
        const int row = r0 + tid;
        gc_s[0][tid] = uwx[row]; gc_s[1][tid] = ub[row];
        gc_s[2][tid] = rwx[row]; gc_s[3][tid] = rb[row];
        gc_s[4][tid] = wx[row];  gc_s[5][tid] = bb[row];
        gc_s[6][tid] = v[row];
    }

    // prologue: pin first `ncache` U-rows of this CTA into SMEM
    {
        const uint4* src = ((const uint4*)g_wu) + (size_t)r0 * ROW_U4;
        const int n = ncache * ROW_U4;
        for (int i = tid; i < n; i += BLOCK) ws[i] = src[i];
    }

    // matvec row pointers (warp w owns row r0+w for all three matrices)
    const bool mv_active = (warp < nrows);
    const int  myrow = r0 + warp;
    const uint4* pu = nullptr; const uint4* pr = nullptr; const uint4* pc = nullptr;
    if (mv_active) {
        const size_t off = (size_t)myrow * ROW_U4;
        pu = (warp < ncache) ? (ws + (size_t)warp * ROW_U4)
                             : (((const uint4*)g_wu) + off);
        pr = ((const uint4*)g_wr) + off;
        pc = ((const uint4*)g_wc) + off;
    }

    const float c0 = cc[0];
    unsigned phase = 0;
    const int total_steps = T_TRAIN + horizon;
    __syncthreads();   // flags/constants/ws visible to all warps

    for (int t = 0; t < total_steps; ++t) {
        const int par = t & 1;
        const float* hin  = g_h[par];
        float*       hout = g_h[par ^ 1];
        const bool need_y = (t >= T_TRAIN - 1);

        if (warp >= DOTW) {
            // ---- stager warps: convert fp32 h -> packed-permuted fp16 ----
            const int sw  = warp - DOTW;        // 0..3
            const int sid = tid - DOTW * 32;    // 0..127

            // warp 31: publish x FIRST so dot warps never wait at the tail
            if (warp == 31) {
                if (t < T_TRAIN) {
                    if (lane == 0) {
                        x_s = x_seq[t];
                        __threadfence_block();
                        flX = t;
                    }
                } else {
                    const float* p = g_vhp[t - T_TRAIN];
                    float s = 0.f;
                    for (int i = lane; i < G; i += 32) s += p[i];
                    #pragma unroll
                    for (int o = 16; o; o >>= 1)
                        s += __shfl_down_sync(0xffffffffu, s, o);
                    if (lane == 0) {
                        x_s = s + c0;
                        __threadfence_block();
                        flX = t;
                    }
                }
            }

            const float4* src = (const float4*)hin;
            // chunk A: j in [0,256)  (dot batches k<8)
            #pragma unroll
            for (int i = sid; i < 256; i += 128) {
                float4 a = src[i];
                float4 bq = src[512 + i];
                uint4 o; __half2 tt;
                tt = __floats2half2_rn(a.x,  a.y);  o.x = *(unsigned*)&tt;
                tt = __floats2half2_rn(a.z,  a.w);  o.y = *(unsigned*)&tt;
                tt = __floats2half2_rn(bq.x, bq.y); o.z = *(unsigned*)&tt;
                tt = __floats2half2_rn(bq.z, bq.w); o.w = *(unsigned*)&tt;
                h2s[i] = o;
            }
            __syncwarp();
            __threadfence_block();
            if (lane == 0) flA[sw] = t;
            // chunk B: j in [256,512)  (dot batches k>=8)
            #pragma unroll
            for (int i = sid + 256; i < 512; i += 128) {
                float4 a = src[i];
                float4 bq = src[512 + i];
                uint4 o; __half2 tt;
                tt = __floats2half2_rn(a.x,  a.y);  o.x = *(unsigned*)&tt;
                tt = __floats2half2_rn(a.z,  a.w);  o.y = *(unsigned*)&tt;
                tt = __floats2half2_rn(bq.x, bq.y); o.z = *(unsigned*)&tt;
                tt = __floats2half2_rn(bq.z, bq.w); o.w = *(unsigned*)&tt;
                h2s[i] = o;
            }
            __syncwarp();
            __threadfence_block();
            if (lane == 0) flB[sw] = t;
        } else if (mv_active) {
            // ---- dot warps: merged 16-batch loop, packed-half partials ----
            const float h_old = hin[myrow];     // fp32 state read, issued early
            unsigned long long au = 0ull, ar = 0ull, ac = 0ull;

            uint4 wu0 = pu[lane], wr0 = pr[lane], wc0 = pc[lane];  // pre-wait
            wait_flags(flA, t);
            #pragma unroll
            for (int k = 0; k < 16; ++k) {
                const int j = lane + 32 * k;   // compile-time offset after unroll
                uint4 nu, nr, nc;
                if (k < 15) {                  // folds away (full unroll)
                    nu = pu[j + 32]; nr = pr[j + 32]; nc = pc[j + 32];
                }
                if (k == 8) wait_flags(flB, t);   // batch-8 weights already in flight
                uint4 hh = h2s[j];             // 8 fp16 h, permuted-packed
                float2 fu = dot8h(wu0, hh);
                float2 fr = dot8h(wr0, hh);
                float2 fc = dot8h(wc0, hh);
                fadd2(au, fu.x, fu.y);
                fadd2(ar, fr.x, fr.y);
                fadd2(ac, fc.x, fc.y);
                if (k < 15) { wu0 = nu; wr0 = nr; wc0 = nc; }
            }

            float su = hsum2(au), sr = hsum2(ar), sc = hsum2(ac);
            #pragma unroll
            for (int o = 16; o; o >>= 1) {
                su += __shfl_down_sync(0xffffffffu, su, o);
                sr += __shfl_down_sync(0xffffffffu, sr, o);
                sc += __shfl_down_sync(0xffffffffu, sc, o);
            }

            // decentralized gate: lane 0 updates its own row (fp32 chain)
            if (lane == 0) {
                volatile int* fx = &flX;
                while (*fx < t) { }            // long since set
                const float x = x_s;
                const float u  = sigmoidf_fast(gc_s[0][warp] * x + su + gc_s[1][warp]);
                const float r  = sigmoidf_fast(gc_s[2][warp] * x + sr + gc_s[3][warp]);
                const float hh = tanhf(gc_s[4][warp] * x + r * sc + gc_s[5][warp]);
                const float hn = h_old + u * (hh - h_old);
                hout[myrow] = hn;
                if (need_y) red_s[warp] = gc_s[6][warp] * hn;
            }
        }

        // y partial reduction only on the last horizon+1 steps
        if (need_y) {
            __syncthreads();
            if (warp == 0) {
                float yv = (lane < nrows) ? red_s[lane] : 0.f;
                #pragma unroll
                for (int o = 16; o; o >>= 1)
                    yv += __shfl_down_sync(0xffffffffu, yv, o);
                if (lane == 0) g_vhp[t - (T_TRAIN - 1)][b] = yv;
            }
        }

        grid_barrier(phase, G);
    }

    // emit predictions (deterministic final reduction)
    if (b == 0 && tid < horizon) {
        const float* p = g_vhp[tid + 1];
        float s = 0.f;
        for (int i = 0; i < G; ++i) s += p[i];
        out[tid] = s + c0;
    }
}

// ---------------- launch ----------------------------------------------------
extern "C" void kernel_launch(void* const* d_in, const int* in_sizes, int n_in,
                              void* d_out, int out_size)
{
    (void)in_sizes; (void)n_in;
    const float* x_seq = (const float*)d_in[0];
    // d_in[1] is the scalar 'horizon' (int32); we use out_size instead.
    const float* uwx = (const float*)d_in[2];
    const float* uWh = (const float*)d_in[3];
    const float* ub  = (const float*)d_in[4];
    const float* rwx = (const float*)d_in[5];
    const float* rWh = (const float*)d_in[6];
    const float* rb  = (const float*)d_in[7];
    const float* wx  = (const float*)d_in[8];
    const float* Wh  = (const float*)d_in[9];
    const float* bb  = (const float*)d_in[10];
    const float* v   = (const float*)d_in[11];
    const float* cc  = (const float*)d_in[12];

    int horizon = out_size;
    if (horizon > HMAX) horizon = HMAX;

    // reset persistent state (graph-capturable, deterministic per replay)
    void* p;
    cudaGetSymbolAddress(&p, g_h);     cudaMemsetAsync(p, 0, sizeof(float) * 2 * H);
    cudaGetSymbolAddress(&p, g_count); cudaMemsetAsync(p, 0, sizeof(unsigned));
    cudaGetSymbolAddress(&p, g_phase); cudaMemsetAsync(p, 0, sizeof(unsigned));

    // fp32 -> fp16 permuted weight conversion
    {
        const int total = H * ROW_U4;
        convert_w<<<(total + 255) / 256, 256>>>(uWh, rWh, Wh);
    }

    // dyn-smem: try 27-row cache, then 26, then none (same decision every call)
    const int base = H2_U4 * (int)sizeof(uint4);      // 8 KB packed fp16 h
    int ncache = NCACHE;
    int dyn    = base + NCACHE * ROW_U4 * (int)sizeof(uint4);
    cudaError_t e = cudaFuncSetAttribute(gru_persistent,
                                         cudaFuncAttributeMaxDynamicSharedMemorySize,
                                         dyn);
    if (e != cudaSuccess) {
        (void)cudaGetLastError();
        ncache = 26;
        dyn    = base + 26 * ROW_U4 * (int)sizeof(uint4);
        e = cudaFuncSetAttribute(gru_persistent,
                                 cudaFuncAttributeMaxDynamicSharedMemorySize,
                                 dyn);
        if (e != cudaSuccess) {
            (void)cudaGetLastError();
            ncache = 0;
            dyn    = base;
        }
    }

    gru_persistent<<<GRID, BLOCK, dyn>>>(x_seq,
                                         uwx, ub,
                                         rwx, rb,
                                         wx,  bb,
                                         v,   cc,
                                         (float*)d_out, horizon, ncache);
}